// round 12
// baseline (speedup 1.0000x reference)
#include <cuda_runtime.h>
#include <cuda_fp16.h>
#include <mma.h>
#include <cstdint>

using namespace nvcuda;

#define NN 8192
#define CC 256

// ---------------------------------------------------------------------------
// Scratch (__device__ globals; allocation-free rule)
// ---------------------------------------------------------------------------
__device__ float  g_s[NN];                       // d^{-1/2}
__device__ __half g_adjh[(size_t)NN * NN];       // fp16(adj), produced in-loop
__device__ __half g_xsh[NN * CC];                // fp16(s_j * x[j][n])  [K][N]
__device__ __half g_a2h[NN * CC];                // fp16(s_i*(t + s_i*x)) [M][K]
__device__ __half g_wh[CC * CC];                 // fp16(w)  [K][N]
__device__ int    g_pcnt[128];                   // per-panel arrival counter
__device__ int    g_done[64];                    // phase-2 handshake

// ---------------------------------------------------------------------------
__device__ __forceinline__ uint32_t smem_u32(const void* p) {
    uint32_t a;
    asm("{ .reg .u64 t; cvta.to.shared.u64 t, %1; cvt.u32.u64 %0, t; }" : "=r"(a) : "l"(p));
    return a;
}
__device__ __forceinline__ void cpa16(uint32_t s, const void* g) {
    asm volatile("cp.async.cg.shared.global [%0], [%1], 16;" :: "r"(s), "l"(g));
}
#define CP_COMMIT() asm volatile("cp.async.commit_group;" ::: "memory")
#define CP_WAIT_2() asm volatile("cp.async.wait_group 2;" ::: "memory")

// ---------------------------------------------------------------------------
// prep kernel: rowsum -> s, xsh = fp16(s_j x[j,:]), w -> fp16, counters reset.
// blocks 0..1023: one warp per adj row (8 rows/block).
// blocks 1024..1087: w convert. block 1088: counter reset.
// ---------------------------------------------------------------------------
__global__ void prep_kernel(const float* __restrict__ adj,
                            const float* __restrict__ x,
                            const float* __restrict__ w) {
    if (blockIdx.x >= 1024) {
        const int t = threadIdx.y * 32 + threadIdx.x;
        if (blockIdx.x == 1088) {
            if (t < 128) g_pcnt[t] = 0;
            if (t < 64) g_done[t] = 0;
            return;
        }
        const int idx = (blockIdx.x - 1024) * 256 + t;   // over CC*CC/4 float4
        float4 v = reinterpret_cast<const float4*>(w)[idx];
        __half2 h0 = __floats2half2_rn(v.x, v.y);
        __half2 h1 = __floats2half2_rn(v.z, v.w);
        uint2 u;
        u.x = *reinterpret_cast<uint32_t*>(&h0);
        u.y = *reinterpret_cast<uint32_t*>(&h1);
        reinterpret_cast<uint2*>(g_wh)[idx] = u;
        return;
    }
    const int row = blockIdx.x * blockDim.y + threadIdx.y;
    const int lane = threadIdx.x;
    const float4* p = reinterpret_cast<const float4*>(adj + (size_t)row * NN);
    float sum = 0.0f;
#pragma unroll 8
    for (int i = lane; i < NN / 4; i += 32) {
        float4 v = __ldcs(p + i);
        sum += (v.x + v.y) + (v.z + v.w);
    }
#pragma unroll
    for (int o = 16; o > 0; o >>= 1) sum += __shfl_xor_sync(0xffffffffu, sum, o);
    const float s = rsqrtf(__shfl_sync(0xffffffffu, sum, 0) + 1.0f);
    if (lane == 0) g_s[row] = s;

    const float4* xp = reinterpret_cast<const float4*>(x + (size_t)row * CC);
    uint2* xo = reinterpret_cast<uint2*>(g_xsh + (size_t)row * CC);
#pragma unroll
    for (int i = lane; i < CC / 4; i += 32) {
        float4 v = xp[i];
        __half2 h0 = __floats2half2_rn(s * v.x, s * v.y);
        __half2 h1 = __floats2half2_rn(s * v.z, s * v.w);
        uint2 u;
        u.x = *reinterpret_cast<uint32_t*>(&h0);
        u.y = *reinterpret_cast<uint32_t*>(&h1);
        xo[i] = u;
    }
}

// ---------------------------------------------------------------------------
// GEMM tiling (R4 champion structure)
// ---------------------------------------------------------------------------
constexpr int BM = 128, BN = 128, BK = 64, STAGES = 4;
constexpr int APAD = 72;
constexpr int BPAD = 136;
constexpr int A_HALVES = BM * APAD;        // 9216
constexpr int B_HALVES = BK * BPAD;        // 8704
constexpr int STAGE_BYTES = (A_HALVES + B_HALVES) * 2;   // 35840
constexpr int SMEM_BYTES = STAGES * STAGE_BYTES;          // 143360

// generic mainloop (used for phase 2; no production hooks)
__device__ __forceinline__ void gemm_mainloop(
    const __half* __restrict__ gA, size_t kA,
    const __half* __restrict__ gB, int k_iters,
    uint32_t sb, uint32_t sAo, uint32_t sBo, const char* smem,
    int wm, int wn,
    wmma::fragment<wmma::accumulator, 16, 16, 16, float> (&acc)[2][4]) {

    auto load_stage = [&](int kt, int s) {
        const uint32_t st = sb + s * STAGE_BYTES;
        const __half* a = gA + (size_t)kt * BK;
        const __half* b = gB + (size_t)kt * BK * CC;
#pragma unroll
        for (int r = 0; r < 4; r++)
            cpa16(st + sAo + r * (32 * APAD * 2), a + (size_t)(r * 32) * kA);
#pragma unroll
        for (int r = 0; r < 4; r++)
            cpa16(st + sBo + r * (16 * BPAD * 2), b + (size_t)(r * 16) * CC);
    };

#pragma unroll
    for (int s = 0; s < STAGES - 1; s++) {
        if (s < k_iters) load_stage(s, s);
        CP_COMMIT();
    }
    for (int kt = 0; kt < k_iters; kt++) {
        CP_WAIT_2();
        __syncthreads();
        const int nk = kt + STAGES - 1;
        if (nk < k_iters) load_stage(nk, nk & 3);
        CP_COMMIT();

        const __half* Ap = reinterpret_cast<const __half*>(smem + (kt & 3) * STAGE_BYTES);
        const __half* Bp = Ap + A_HALVES;
        wmma::fragment<wmma::matrix_a, 16, 16, 16, __half, wmma::row_major> af[2][2];
        wmma::fragment<wmma::matrix_b, 16, 16, 16, __half, wmma::row_major> bf[2][4];
#pragma unroll
        for (int i = 0; i < 2; i++)
            wmma::load_matrix_sync(af[0][i], Ap + (wm * 32 + i * 16) * APAD, APAD);
#pragma unroll
        for (int j = 0; j < 4; j++)
            wmma::load_matrix_sync(bf[0][j], Bp + wn * 64 + j * 16, BPAD);
#pragma unroll
        for (int ks = 0; ks < 4; ks++) {
            const int cu = ks & 1, nx = cu ^ 1;
            if (ks < 3) {
#pragma unroll
                for (int i = 0; i < 2; i++)
                    wmma::load_matrix_sync(af[nx][i],
                        Ap + (wm * 32 + i * 16) * APAD + (ks + 1) * 16, APAD);
#pragma unroll
                for (int j = 0; j < 4; j++)
                    wmma::load_matrix_sync(bf[nx][j],
                        Bp + ((ks + 1) * 16) * BPAD + wn * 64 + j * 16, BPAD);
            }
#pragma unroll
            for (int i = 0; i < 2; i++)
#pragma unroll
                for (int j = 0; j < 4; j++)
                    wmma::mma_sync(acc[i][j], af[cu][i], bf[cu][j], acc[i][j]);
        }
    }
    __syncthreads();
}

// ---------------------------------------------------------------------------
// Fused kernel. Phase 1: in-loop panel-ordered adj->adjh conversion feeding
// the t-GEMM via arrival counters. Phase 2: out = ELU(a2h @ wh).
// 128 CTAs, 1/SM, all wave-1 resident.
// ---------------------------------------------------------------------------
__global__ __launch_bounds__(256, 1)
void gcn_fused(const float* __restrict__ adj, const float* __restrict__ xin,
               float* __restrict__ outp) {
    extern __shared__ char smem[];
    const uint32_t sb = smem_u32(smem);
    const int tid = threadIdx.x;
    const int warp = tid >> 5;
    const int wm = warp & 3;
    const int wn = warp >> 2;
    const int m0 = blockIdx.y * BM;
    const int n0 = blockIdx.x * BN;
    const int cid = blockIdx.y * 2 + blockIdx.x;     // 0..127

    // gemm load coords
    const int arr = tid >> 3, arc = (tid & 7) * 8;
    const int brr = tid >> 4, brc = (tid & 15) * 8;
    const uint32_t sAo = (arr * APAD + arc) * 2;
    const uint32_t sBo = A_HALVES * 2 + (brr * BPAD + brc) * 2;

    // panel-production coords: CTA cid owns rows cid*64 .. +63 of every panel
    const int prl = tid >> 2;            // 0..63
    const int pc0 = (tid & 3) * 16;      // 0/16/32/48
    const size_t prow = (size_t)(cid * 64 + prl) * NN + pc0;

    float4 areg[4];
    auto ldg_panel = [&](int p) {
        const float4* src = reinterpret_cast<const float4*>(adj + prow + (size_t)p * 64);
#pragma unroll
        for (int r = 0; r < 4; r++) areg[r] = __ldcs(src + r);
    };
    auto stg_panel = [&](int p) {
        uint4 u0, u1;
        __half2* h0 = reinterpret_cast<__half2*>(&u0);
        __half2* h1 = reinterpret_cast<__half2*>(&u1);
        h0[0] = __floats2half2_rn(areg[0].x, areg[0].y);
        h0[1] = __floats2half2_rn(areg[0].z, areg[0].w);
        h0[2] = __floats2half2_rn(areg[1].x, areg[1].y);
        h0[3] = __floats2half2_rn(areg[1].z, areg[1].w);
        h1[0] = __floats2half2_rn(areg[2].x, areg[2].y);
        h1[1] = __floats2half2_rn(areg[2].z, areg[2].w);
        h1[2] = __floats2half2_rn(areg[3].x, areg[3].y);
        h1[3] = __floats2half2_rn(areg[3].z, areg[3].w);
        uint4* dst = reinterpret_cast<uint4*>(g_adjh + prow + (size_t)p * 64);
        dst[0] = u0;
        dst[1] = u1;
    };

    const __half* gA = g_adjh + (size_t)(m0 + arr) * NN + arc;
    const __half* gB = g_xsh + (size_t)brr * CC + n0 + brc;
    auto load_stage1 = [&](int kt, int s) {
        const uint32_t st = sb + s * STAGE_BYTES;
        const __half* a = gA + (size_t)kt * BK;
        const __half* b = gB + (size_t)kt * BK * CC;
#pragma unroll
        for (int r = 0; r < 4; r++)
            cpa16(st + sAo + r * (32 * APAD * 2), a + (size_t)(r * 32) * NN);
#pragma unroll
        for (int r = 0; r < 4; r++)
            cpa16(st + sBo + r * (16 * BPAD * 2), b + (size_t)(r * 16) * CC);
    };

    wmma::fragment<wmma::accumulator, 16, 16, 16, float> acc[2][4];
#pragma unroll
    for (int i = 0; i < 2; i++)
#pragma unroll
        for (int j = 0; j < 4; j++) wmma::fill_fragment(acc[i][j], 0.0f);

    // ===== phase-1 prologue: produce panels 0..7, prefetch 8, prime pipeline
#pragma unroll 1
    for (int q = 0; q < 8; q++) { ldg_panel(q); stg_panel(q); }
    __threadfence();
    __syncthreads();
    if (tid == 0)
        for (int q = 0; q < 8; q++) atomicAdd(&g_pcnt[q], 1);
    ldg_panel(8);
    if (tid == 0)
        for (int q = 0; q < 3; q++)
            while (*(volatile int*)&g_pcnt[q] < 128) __nanosleep(64);
    __syncthreads();
    __threadfence();
#pragma unroll
    for (int s = 0; s < 3; s++) { load_stage1(s, s); CP_COMMIT(); }

    // ===== phase-1 mainloop (k_iters = 128)
    for (int kt = 0; kt < 128; kt++) {
        if (kt < 120) { stg_panel(kt + 8); __threadfence(); }
        if (kt < 119) ldg_panel(kt + 9);
        CP_WAIT_2();
        __syncthreads();
        if (tid == 0) {
            if (kt < 120) atomicAdd(&g_pcnt[kt + 8], 1);
            if (kt < 125)
                while (*(volatile int*)&g_pcnt[kt + 3] < 128) __nanosleep(32);
        }
        __syncthreads();
        if (kt < 125) load_stage1(kt + 3, (kt + 3) & 3);
        CP_COMMIT();

        const __half* Ap = reinterpret_cast<const __half*>(smem + (kt & 3) * STAGE_BYTES);
        const __half* Bp = Ap + A_HALVES;
        wmma::fragment<wmma::matrix_a, 16, 16, 16, __half, wmma::row_major> af[2][2];
        wmma::fragment<wmma::matrix_b, 16, 16, 16, __half, wmma::row_major> bf[2][4];
#pragma unroll
        for (int i = 0; i < 2; i++)
            wmma::load_matrix_sync(af[0][i], Ap + (wm * 32 + i * 16) * APAD, APAD);
#pragma unroll
        for (int j = 0; j < 4; j++)
            wmma::load_matrix_sync(bf[0][j], Bp + wn * 64 + j * 16, BPAD);
#pragma unroll
        for (int ks = 0; ks < 4; ks++) {
            const int cu = ks & 1, nx = cu ^ 1;
            if (ks < 3) {
#pragma unroll
                for (int i = 0; i < 2; i++)
                    wmma::load_matrix_sync(af[nx][i],
                        Ap + (wm * 32 + i * 16) * APAD + (ks + 1) * 16, APAD);
#pragma unroll
                for (int j = 0; j < 4; j++)
                    wmma::load_matrix_sync(bf[nx][j],
                        Bp + ((ks + 1) * 16) * BPAD + wn * 64 + j * 16, BPAD);
            }
#pragma unroll
            for (int i = 0; i < 2; i++)
#pragma unroll
                for (int j = 0; j < 4; j++)
                    wmma::mma_sync(acc[i][j], af[cu][i], bf[cu][j], acc[i][j]);
        }
    }
    __syncthreads();

    // ===== phase-1 epilogue: a2h = fp16( s_i * (t + s_i * x) )
    float* stg = reinterpret_cast<float*>(smem);   // 128 x 132
#pragma unroll
    for (int i = 0; i < 2; i++)
#pragma unroll
        for (int j = 0; j < 4; j++)
            wmma::store_matrix_sync(stg + (wm * 32 + i * 16) * 132 + wn * 64 + j * 16,
                                    acc[i][j], 132, wmma::mem_row_major);
    __syncthreads();
    {
        const int r = tid >> 1;
        const int c0 = (tid & 1) * 64;
        const int grow = m0 + r;
        const float sA = g_s[grow];
#pragma unroll
        for (int c = 0; c < 64; c += 4) {
            float4 v = *reinterpret_cast<const float4*>(stg + r * 132 + c0 + c);
            const int gcol = n0 + c0 + c;
            const float4 xv = *reinterpret_cast<const float4*>(xin + (size_t)grow * CC + gcol);
            __half2 h0 = __floats2half2_rn(sA * (v.x + sA * xv.x), sA * (v.y + sA * xv.y));
            __half2 h1 = __floats2half2_rn(sA * (v.z + sA * xv.z), sA * (v.w + sA * xv.w));
            uint2 u;
            u.x = *reinterpret_cast<uint32_t*>(&h0);
            u.y = *reinterpret_cast<uint32_t*>(&h1);
            *reinterpret_cast<uint2*>(&g_a2h[(size_t)grow * CC + gcol]) = u;
        }
    }

    // ===== handshake with sibling CTA
    __threadfence();
    __syncthreads();
    if (tid == 0) {
        atomicAdd(&g_done[blockIdx.y], 1);
        while (atomicAdd(&g_done[blockIdx.y], 0) < 2) __nanosleep(64);
    }
    __syncthreads();
    __threadfence();

    // ===== phase 2: out = ELU( a2h @ wh )
#pragma unroll
    for (int i = 0; i < 2; i++)
#pragma unroll
        for (int j = 0; j < 4; j++) wmma::fill_fragment(acc[i][j], 0.0f);

    gemm_mainloop(g_a2h + (size_t)(m0 + arr) * CC + arc, CC,
                  g_wh + (size_t)brr * CC + n0 + brc, CC / BK,
                  sb, sAo, sBo, smem, wm, wn, acc);

#pragma unroll
    for (int i = 0; i < 2; i++)
#pragma unroll
        for (int j = 0; j < 4; j++) {
#pragma unroll
            for (int e = 0; e < 8; e++) {
                float v = acc[i][j].x[e];
                acc[i][j].x[e] = (v > 0.0f) ? v : expm1f(v);
            }
            const int r = m0 + wm * 32 + i * 16;
            const int c = n0 + wn * 64 + j * 16;
            wmma::store_matrix_sync(&outp[(size_t)r * CC + c], acc[i][j], CC,
                                    wmma::mem_row_major);
        }
}

// ---------------------------------------------------------------------------
extern "C" void kernel_launch(void* const* d_in, const int* in_sizes, int n_in,
                              void* d_out, int out_size) {
    const float *x = nullptr, *adj = nullptr, *w = nullptr;
    for (int i = 0; i < n_in; i++) {
        if (in_sizes[i] == NN * NN) adj = (const float*)d_in[i];
        else if (in_sizes[i] == NN * CC) x = (const float*)d_in[i];
        else if (in_sizes[i] == CC * CC) w = (const float*)d_in[i];
    }
    float* out = (float*)d_out;

    cudaFuncSetAttribute(gcn_fused, cudaFuncAttributeMaxDynamicSharedMemorySize, SMEM_BYTES);

    // rowsum + xsh + w + counter reset (no adjh pass!)
    prep_kernel<<<1089, dim3(32, 8)>>>(adj, x, w);
    // fused: in-loop panel conversion + gemm1 + gemm2. 128 CTAs, all resident.
    gcn_fused<<<dim3(2, 64), 256, SMEM_BYTES>>>(adj, x, out);
}

// round 14
// speedup vs baseline: 1.7435x; 1.7435x over previous
#include <cuda_runtime.h>
#include <cuda_fp16.h>
#include <mma.h>
#include <cstdint>

using namespace nvcuda;

#define NN 8192
#define CC 256

// ---------------------------------------------------------------------------
// Scratch (__device__ globals; allocation-free rule)
// ---------------------------------------------------------------------------
__device__ float  g_s[NN];                       // d^{-1/2}
__device__ __half g_adjh[(size_t)NN * NN];       // fp16(adj)
__device__ __half g_xsh[NN * CC];                // fp16(s_j * x[j][n])  [K][N]
__device__ __half g_a2h[NN * CC];                // fp16(s_i*(t + s_i*x)) [M][K]
__device__ __half g_wh[CC * CC];                 // fp16(w)  [K][N]

// ---------------------------------------------------------------------------
__device__ __forceinline__ uint32_t smem_u32(const void* p) {
    uint32_t a;
    asm("{ .reg .u64 t; cvta.to.shared.u64 t, %1; cvt.u32.u64 %0, t; }" : "=r"(a) : "l"(p));
    return a;
}
__device__ __forceinline__ void cpa16(uint32_t s, const void* g) {
    asm volatile("cp.async.cg.shared.global [%0], [%1], 16;" :: "r"(s), "l"(g));
}
#define CP_COMMIT() asm volatile("cp.async.commit_group;" ::: "memory")
#define CP_WAIT_2() asm volatile("cp.async.wait_group 2;" ::: "memory")
#define CP_WAIT_0() asm volatile("cp.async.wait_group 0;" ::: "memory")

// ---------------------------------------------------------------------------
// prep: blocks 0..1023 -> one warp per adj row: rowsum -> s, adjh, xsh.
//       blocks 1024..1087 -> w convert.
// ---------------------------------------------------------------------------
__global__ void prep_kernel(const float* __restrict__ adj,
                            const float* __restrict__ x,
                            const float* __restrict__ w) {
    if (blockIdx.x >= 1024) {
        const int t = threadIdx.y * 32 + threadIdx.x;
        const int idx = (blockIdx.x - 1024) * 256 + t;   // over CC*CC/4 float4
        float4 v = reinterpret_cast<const float4*>(w)[idx];
        __half2 h0 = __floats2half2_rn(v.x, v.y);
        __half2 h1 = __floats2half2_rn(v.z, v.w);
        uint2 u;
        u.x = *reinterpret_cast<uint32_t*>(&h0);
        u.y = *reinterpret_cast<uint32_t*>(&h1);
        reinterpret_cast<uint2*>(g_wh)[idx] = u;
        return;
    }
    const int row = blockIdx.x * blockDim.y + threadIdx.y;
    const int lane = threadIdx.x;
    const float4* p = reinterpret_cast<const float4*>(adj + (size_t)row * NN);
    uint2* hout = reinterpret_cast<uint2*>(g_adjh + (size_t)row * NN);
    float sum = 0.0f;
#pragma unroll 8
    for (int i = lane; i < NN / 4; i += 32) {
        float4 v = __ldcs(p + i);
        sum += (v.x + v.y) + (v.z + v.w);
        __half2 h0 = __floats2half2_rn(v.x, v.y);
        __half2 h1 = __floats2half2_rn(v.z, v.w);
        uint2 u;
        u.x = *reinterpret_cast<uint32_t*>(&h0);
        u.y = *reinterpret_cast<uint32_t*>(&h1);
        __stcs(hout + i, u);
    }
#pragma unroll
    for (int o = 16; o > 0; o >>= 1) sum += __shfl_xor_sync(0xffffffffu, sum, o);
    const float s = rsqrtf(__shfl_sync(0xffffffffu, sum, 0) + 1.0f);
    if (lane == 0) g_s[row] = s;

    const float4* xp = reinterpret_cast<const float4*>(x + (size_t)row * CC);
    uint2* xo = reinterpret_cast<uint2*>(g_xsh + (size_t)row * CC);
#pragma unroll
    for (int i = lane; i < CC / 4; i += 32) {
        float4 v = xp[i];
        __half2 h0 = __floats2half2_rn(s * v.x, s * v.y);
        __half2 h1 = __floats2half2_rn(s * v.z, s * v.w);
        uint2 u;
        u.x = *reinterpret_cast<uint32_t*>(&h0);
        u.y = *reinterpret_cast<uint32_t*>(&h1);
        xo[i] = u;
    }
}

// ---------------------------------------------------------------------------
// gemm1 (R4 champion, MODE 0 only): t = adjh @ xsh; epilogue writes
//   g_a2h = fp16( s_i * (t + s_i * x) )
// 128x128 tile, BK=64, 4-stage cp.async, single barrier, reg-dbuf, f32 acc.
// ---------------------------------------------------------------------------
constexpr int BM = 128, BN = 128, BK = 64, STAGES = 4;
constexpr int APAD = 72;
constexpr int BPAD = 136;
constexpr int A_HALVES = BM * APAD;        // 9216
constexpr int B_HALVES = BK * BPAD;        // 8704
constexpr int STAGE_BYTES = (A_HALVES + B_HALVES) * 2;   // 35840
constexpr int SMEM1_BYTES = STAGES * STAGE_BYTES;         // 143360

__global__ __launch_bounds__(256, 1)
void gemm1_kernel(const float* __restrict__ xin) {
    extern __shared__ char smem[];
    const uint32_t sb = smem_u32(smem);
    const int tid = threadIdx.x;
    const int warp = tid >> 5;
    const int wm = warp & 3;     // 0..3 along M
    const int wn = warp >> 2;    // 0..1 along N
    const int m0 = blockIdx.y * BM;
    const int n0 = blockIdx.x * BN;

    const int arr = tid >> 3, arc = (tid & 7) * 8;
    const int brr = tid >> 4, brc = (tid & 15) * 8;
    const __half* gA = g_adjh + (size_t)(m0 + arr) * NN + arc;
    const __half* gB = g_xsh + (size_t)brr * CC + n0 + brc;
    const uint32_t sAo = (arr * APAD + arc) * 2;
    const uint32_t sBo = A_HALVES * 2 + (brr * BPAD + brc) * 2;

    wmma::fragment<wmma::accumulator, 16, 16, 16, float> acc[2][4];
#pragma unroll
    for (int i = 0; i < 2; i++)
#pragma unroll
        for (int j = 0; j < 4; j++) wmma::fill_fragment(acc[i][j], 0.0f);

    auto load_stage = [&](int kt, int s) {
        const uint32_t st = sb + s * STAGE_BYTES;
        const __half* a = gA + kt * BK;
        const __half* b = gB + (size_t)kt * BK * CC;
#pragma unroll
        for (int r = 0; r < 4; r++)
            cpa16(st + sAo + r * (32 * APAD * 2), a + (size_t)(r * 32) * NN);
#pragma unroll
        for (int r = 0; r < 4; r++)
            cpa16(st + sBo + r * (16 * BPAD * 2), b + (size_t)(r * 16) * CC);
    };

#pragma unroll
    for (int s = 0; s < STAGES - 1; s++) {
        load_stage(s, s);
        CP_COMMIT();
    }

    const int k_iters = NN / BK;   // 128
    for (int kt = 0; kt < k_iters; kt++) {
        CP_WAIT_2();
        __syncthreads();

        const int nk = kt + STAGES - 1;
        if (nk < k_iters) load_stage(nk, nk & 3);
        CP_COMMIT();

        const __half* Ap = reinterpret_cast<const __half*>(smem + (kt & 3) * STAGE_BYTES);
        const __half* Bp = Ap + A_HALVES;

        wmma::fragment<wmma::matrix_a, 16, 16, 16, __half, wmma::row_major> af[2][2];
        wmma::fragment<wmma::matrix_b, 16, 16, 16, __half, wmma::row_major> bf[2][4];
#pragma unroll
        for (int i = 0; i < 2; i++)
            wmma::load_matrix_sync(af[0][i], Ap + (wm * 32 + i * 16) * APAD, APAD);
#pragma unroll
        for (int j = 0; j < 4; j++)
            wmma::load_matrix_sync(bf[0][j], Bp + wn * 64 + j * 16, BPAD);

#pragma unroll
        for (int ks = 0; ks < 4; ks++) {
            const int cu = ks & 1, nx = cu ^ 1;
            if (ks < 3) {
#pragma unroll
                for (int i = 0; i < 2; i++)
                    wmma::load_matrix_sync(af[nx][i],
                        Ap + (wm * 32 + i * 16) * APAD + (ks + 1) * 16, APAD);
#pragma unroll
                for (int j = 0; j < 4; j++)
                    wmma::load_matrix_sync(bf[nx][j],
                        Bp + ((ks + 1) * 16) * BPAD + wn * 64 + j * 16, BPAD);
            }
#pragma unroll
            for (int i = 0; i < 2; i++)
#pragma unroll
                for (int j = 0; j < 4; j++)
                    wmma::mma_sync(acc[i][j], af[cu][i], bf[cu][j], acc[i][j]);
        }
    }
    __syncthreads();

    float* stg = reinterpret_cast<float*>(smem);   // 128 x 132
#pragma unroll
    for (int i = 0; i < 2; i++)
#pragma unroll
        for (int j = 0; j < 4; j++)
            wmma::store_matrix_sync(stg + (wm * 32 + i * 16) * 132 + wn * 64 + j * 16,
                                    acc[i][j], 132, wmma::mem_row_major);
    __syncthreads();

    const int r = tid >> 1;
    const int c0 = (tid & 1) * 64;
    const int grow = m0 + r;
    const float sA = g_s[grow];
#pragma unroll
    for (int c = 0; c < 64; c += 4) {
        float4 v = *reinterpret_cast<const float4*>(stg + r * 132 + c0 + c);
        const int gcol = n0 + c0 + c;
        const float4 xv = *reinterpret_cast<const float4*>(xin + (size_t)grow * CC + gcol);
        __half2 h0 = __floats2half2_rn(sA * (v.x + sA * xv.x), sA * (v.y + sA * xv.y));
        __half2 h1 = __floats2half2_rn(sA * (v.z + sA * xv.z), sA * (v.w + sA * xv.w));
        uint2 u;
        u.x = *reinterpret_cast<uint32_t*>(&h0);
        u.y = *reinterpret_cast<uint32_t*>(&h1);
        *reinterpret_cast<uint2*>(&g_a2h[(size_t)grow * CC + gcol]) = u;
    }
}

// ---------------------------------------------------------------------------
// gemm2 single-shot: out = ELU( a2h @ wh ).  Tile 64x128, grid (2,128).
// Entire K=256 loaded into smem in one cp.async burst; 16 k-steps; ELU on
// fragments; direct store (no smem staging).
// 256 threads = 8 warps as 2(M) x 4(N); warp tile 32x32.
// ---------------------------------------------------------------------------
constexpr int AP2 = 264;                         // A row stride (halves), 64r x 256
constexpr int BP2 = 136;                         // B row stride (halves), 256r x 128
constexpr int A2_HALVES = 64 * AP2;              // 16896
constexpr int SMEM2_BYTES = (A2_HALVES + 256 * BP2) * 2;   // 103424

__global__ __launch_bounds__(256, 1)
void gemm2_kernel(float* __restrict__ outp) {
    extern __shared__ char smem[];
    const uint32_t sb = smem_u32(smem);
    const int tid = threadIdx.x;
    const int warp = tid >> 5;
    const int wm = warp & 1;     // 0..1 along M (32 rows)
    const int wn = warp >> 1;    // 0..3 along N (32 cols)
    const int m0 = blockIdx.y * 64;
    const int n0 = blockIdx.x * 128;

    // A: 64 rows x 32 chunks(16B) = 2048 -> 8/thread
    // B: 256 rows x 16 chunks(16B) = 4096 -> 16/thread
    const __half* gA = g_a2h + (size_t)m0 * CC;
    const __half* gB = g_wh + n0;
#pragma unroll
    for (int r = 0; r < 8; r++) {
        const int c = tid + r * 256;
        const int row = c >> 5, col = (c & 31) * 8;
        cpa16(sb + (row * AP2 + col) * 2, gA + (size_t)row * CC + col);
        if ((r & 1) == 1) CP_COMMIT();
    }
#pragma unroll
    for (int r = 0; r < 16; r++) {
        const int c = tid + r * 256;
        const int row = c >> 4, col = (c & 15) * 8;
        cpa16(sb + A2_HALVES * 2 + (row * BP2 + col) * 2, gB + (size_t)row * CC + col);
        if ((r & 3) == 3) CP_COMMIT();
    }
    CP_WAIT_0();
    __syncthreads();

    const __half* Ap = reinterpret_cast<const __half*>(smem);
    const __half* Bp = Ap + A2_HALVES;

    wmma::fragment<wmma::accumulator, 16, 16, 16, float> acc[2][2];
#pragma unroll
    for (int i = 0; i < 2; i++)
#pragma unroll
        for (int j = 0; j < 2; j++) wmma::fill_fragment(acc[i][j], 0.0f);

    wmma::fragment<wmma::matrix_a, 16, 16, 16, __half, wmma::row_major> af[2][2];
    wmma::fragment<wmma::matrix_b, 16, 16, 16, __half, wmma::row_major> bf[2][2];
#pragma unroll
    for (int i = 0; i < 2; i++)
        wmma::load_matrix_sync(af[0][i], Ap + (wm * 32 + i * 16) * AP2, AP2);
#pragma unroll
    for (int j = 0; j < 2; j++)
        wmma::load_matrix_sync(bf[0][j], Bp + wn * 32 + j * 16, BP2);

#pragma unroll
    for (int ks = 0; ks < 16; ks++) {
        const int cu = ks & 1, nx = cu ^ 1;
        if (ks < 15) {
#pragma unroll
            for (int i = 0; i < 2; i++)
                wmma::load_matrix_sync(af[nx][i],
                    Ap + (wm * 32 + i * 16) * AP2 + (ks + 1) * 16, AP2);
#pragma unroll
            for (int j = 0; j < 2; j++)
                wmma::load_matrix_sync(bf[nx][j],
                    Bp + ((ks + 1) * 16) * BP2 + wn * 32 + j * 16, BP2);
        }
#pragma unroll
        for (int i = 0; i < 2; i++)
#pragma unroll
            for (int j = 0; j < 2; j++)
                wmma::mma_sync(acc[i][j], af[cu][i], bf[cu][j], acc[i][j]);
    }

    // ELU on fragments (uniform elementwise -> mapping-safe), direct store
#pragma unroll
    for (int i = 0; i < 2; i++)
#pragma unroll
        for (int j = 0; j < 2; j++) {
#pragma unroll
            for (int e = 0; e < 8; e++) {
                float v = acc[i][j].x[e];
                acc[i][j].x[e] = (v > 0.0f) ? v : expm1f(v);
            }
            const int r = m0 + wm * 32 + i * 16;
            const int c = n0 + wn * 32 + j * 16;
            wmma::store_matrix_sync(&outp[(size_t)r * CC + c], acc[i][j], CC,
                                    wmma::mem_row_major);
        }
}

// ---------------------------------------------------------------------------
extern "C" void kernel_launch(void* const* d_in, const int* in_sizes, int n_in,
                              void* d_out, int out_size) {
    const float *x = nullptr, *adj = nullptr, *w = nullptr;
    for (int i = 0; i < n_in; i++) {
        if (in_sizes[i] == NN * NN) adj = (const float*)d_in[i];
        else if (in_sizes[i] == NN * CC) x = (const float*)d_in[i];
        else if (in_sizes[i] == CC * CC) w = (const float*)d_in[i];
    }
    float* out = (float*)d_out;

    cudaFuncSetAttribute(gemm1_kernel, cudaFuncAttributeMaxDynamicSharedMemorySize, SMEM1_BYTES);
    cudaFuncSetAttribute(gemm2_kernel, cudaFuncAttributeMaxDynamicSharedMemorySize, SMEM2_BYTES);

    // rowsum + adjh + xsh + w, one launch
    prep_kernel<<<1088, dim3(32, 8)>>>(adj, x, w);
    // gemm1: blockIdx.x = n-half (fast) -> adj row-tile pair co-resident,
    // L2 dedups the A read.
    gemm1_kernel<<<dim3(2, 64), 256, SMEM1_BYTES>>>(x);
    // gemm2: 256 CTAs, single-shot smem, latency-optimized
    gemm2_kernel<<<dim3(2, 128), 256, SMEM2_BYTES>>>(out);
}